// round 6
// baseline (speedup 1.0000x reference)
#include <cuda_runtime.h>
#include <cuda_bf16.h>
#include <cstdint>

typedef __nv_bfloat16 bf16;

#define BB   128
#define TT   256
#define NH   1024
#define NI   1024
#define NT   512              // threads per CTA (16 warps)
#define KB   64               // k per chunk
#define KC   256              // k-slice per tile
#define NC   (KC/KB)          // 4 chunks per tile

// padded rows: 64 k-elems + 8 pad = 72 elems = 144 bytes (LDSM conflict-free)
#define ROWB 144
#define A_REGION (2*2*128*ROWB)            // [ver][buf][row]  = 73728 B
#define B_REGION (2*2*64*ROWB)             // [ver][buf][n]    = 36864 B
#define SMEM_DYN (A_REGION + B_REGION)
#define CHUNK_BYTES (49152u)               // (2*128 + 2*64) rows * 128 B

// ---------------- device scratch ----------------
__device__ __align__(16) float g_s [9][BB*NH];
__device__ __align__(16) bf16  g_sh[6][BB*NH];
__device__ __align__(16) bf16  g_sl[6][BB*NH];
__device__ __align__(16) float g_hbuf[BB*NH];
__device__ __align__(16) bf16  g_hh[BB*NH];
__device__ __align__(16) bf16  g_hl[BB*NH];
__device__ __align__(16) bf16  g_xh[BB*TT*NI];
__device__ __align__(16) bf16  g_xl[BB*TT*NI];
__device__ __align__(16) bf16  g_W0th[2048*2048];     // [n][k] hi
__device__ __align__(16) bf16  g_W0tl[2048*2048];     // [n][k] lo
__device__ __align__(16) bf16  g_Wsth[8][2048*1024];  // [n][k] hi per gene
__device__ __align__(16) bf16  g_Wstl[8][2048*1024];  // [n][k] lo per gene
__device__ __align__(16) float g_part[8*3][BB*2048];  // [slice*3+slot][row][gcol]
__device__ unsigned g_arrive, g_epoch;

// ---------------- primitives ----------------
__device__ __forceinline__ void mma16816(float c[4], const uint32_t a[4],
                                         uint32_t b0, uint32_t b1){
  asm volatile(
    "mma.sync.aligned.m16n8k16.row.col.f32.bf16.bf16.f32 "
    "{%0,%1,%2,%3},{%4,%5,%6,%7},{%8,%9},{%0,%1,%2,%3};\n"
    : "+f"(c[0]), "+f"(c[1]), "+f"(c[2]), "+f"(c[3])
    : "r"(a[0]), "r"(a[1]), "r"(a[2]), "r"(a[3]), "r"(b0), "r"(b1));
}

__device__ __forceinline__ void ldsm4(uint32_t r[4], uint32_t addr){
  asm volatile("ldmatrix.sync.aligned.m8n8.x4.shared.b16 {%0,%1,%2,%3}, [%4];"
    : "=r"(r[0]), "=r"(r[1]), "=r"(r[2]), "=r"(r[3]) : "r"(addr));
}

__device__ __forceinline__ void bulk128(uint32_t dst, const void* src, uint32_t mbar){
  asm volatile(
    "cp.async.bulk.shared::cta.global.mbarrier::complete_tx::bytes [%0], [%1], %2, [%3];"
    :: "r"(dst), "l"(src), "r"(128u), "r"(mbar) : "memory");
}

__device__ __forceinline__ void expect_tx(uint32_t mbar, uint32_t bytes){
  asm volatile("mbarrier.arrive.expect_tx.shared.b64 _, [%0], %1;"
    :: "r"(mbar), "r"(bytes) : "memory");
}

__device__ __forceinline__ void mbar_wait(uint32_t mbar, int phase){
  uint32_t done;
  asm volatile(
    "{\n\t.reg .pred p;\n\t"
    "mbarrier.try_wait.parity.acquire.cta.shared::cta.b64 p, [%1], %2;\n\t"
    "selp.b32 %0, 1, 0, p;\n\t}"
    : "=r"(done) : "r"(mbar), "r"((uint32_t)phase) : "memory");
  if (!done){
    asm volatile(
      "{\n\t.reg .pred P1;\n\t"
      "WAIT_LOOP_%=:\n\t"
      "mbarrier.try_wait.parity.acquire.cta.shared::cta.b64 P1, [%0], %1, 0x989680;\n\t"
      "@P1 bra.uni WAIT_DONE_%=;\n\t"
      "bra.uni WAIT_LOOP_%=;\n\t"
      "WAIT_DONE_%=:\n\t}"
      :: "r"(mbar), "r"((uint32_t)phase) : "memory");
  }
}

__device__ __forceinline__ void gsync(unsigned &target){
  __syncthreads();
  if (threadIdx.x == 0){
    target += gridDim.x;
    unsigned old;
    asm volatile("atom.add.release.gpu.global.u32 %0, [%1], %2;"
                 : "=r"(old) : "l"(&g_arrive), "r"(1u) : "memory");
    if (old + 1 == target){
      asm volatile("st.release.gpu.global.u32 [%0], %1;" :: "l"(&g_epoch), "r"(target) : "memory");
    } else {
      unsigned e; int spins = 0;
      do {
        asm volatile("ld.acquire.gpu.global.u32 %0, [%1];" : "=r"(e) : "l"(&g_epoch) : "memory");
        if (++spins > 32) __nanosleep(64);
      } while ((int)(e - target) < 0);
    }
  }
  __syncthreads();
}

__device__ __forceinline__ float act_fn(int act, float v){
  switch (act){
    case 0:  return 1.f/(1.f + __expf(-v));
    case 1:  return fmaxf(v, 0.f);
    case 2:  return v;
    default: return tanhf(v);
  }
}

__device__ __forceinline__ uint32_t A_off(int ver, int buf, int row){
  return (uint32_t)(((ver*2+buf)*128 + row)*ROWB);
}
__device__ __forceinline__ uint32_t B_off(int ver, int buf, int n){
  return (uint32_t)(A_REGION + ((ver*2+buf)*64 + n)*ROWB);
}

// ---------------- split-K GEMM tile (3-term: AhWh + AlWh + AhWl) ----------------
// M=128 rows, NLOC=64 local cols: n<32 -> gcol=j+n (c-half); n>=32 -> 1024+j+(n-32) (h-half).
// 16 warps as 8(M)x2(N): warp = 16 rows x 32 n (16 c + 16 h, pair in same thread).
// K-slice KC=256 as 4 chunks of 64, double-buffered via cp.async.bulk + mbarrier.
__device__ void gemm_tile(
    const bf16* __restrict__ ah, const bf16* __restrict__ al, long astr,
    const bf16* __restrict__ wh, const bf16* __restrict__ wl, int Kw,
    float* __restrict__ part, int j,
    uint32_t sbase, uint32_t mb0, int ph[2], int tid)
{
  const int lane = tid & 31, warp = tid >> 5;
  const int wm = warp >> 1, wn = warp & 1;

  float C[4][4];
  #pragma unroll
  for (int n=0;n<4;n++)
    #pragma unroll
    for (int q=0;q<4;q++) C[n][q]=0.f;

  auto load_chunk = [&](int c, int b){
    if (tid < 384){
      int k0 = c*KB;
      uint32_t mbar = mb0 + b*8;
      if (tid < 256){
        int ver = tid >> 7, row = tid & 127;
        const bf16* src = (ver ? al : ah) + (size_t)row*astr + k0;
        bulk128(sbase + A_off(ver,b,row), src, mbar);
      } else {
        int id = tid - 256;
        int ver = id >> 6, n = id & 63;
        int gcol = (n < 32) ? (j + n) : (NH + j + (n - 32));
        const bf16* src = (ver ? wl : wh) + (size_t)gcol*Kw + k0;
        bulk128(sbase + B_off(ver,b,n), src, mbar);
      }
    }
  };

  // preload chunks 0,1
  if (tid == 0){ expect_tx(mb0, CHUNK_BYTES); expect_tx(mb0+8, CHUNK_BYTES); }
  __syncthreads();
  load_chunk(0,0);
  load_chunk(1,1);

  // per-lane LDSM address components (byte offsets)
  const uint32_t a_row  = (uint32_t)(wm*16 + (lane & 15));
  const uint32_t a_koff = (uint32_t)((lane >> 4) * 16);          // 8 elems * 2B
  const int sub = lane >> 3;
  const uint32_t b_n    = (uint32_t)(wn*16 + ((sub >> 1) << 3) + (lane & 7));
  const uint32_t b_koff = (uint32_t)((sub & 1) * 16);

  #pragma unroll
  for (int c=0; c<NC; c++){
    const int b = c & 1;
    const uint32_t mbar = mb0 + b*8;
    mbar_wait(mbar, ph[b]); ph[b] ^= 1;
    if (c + 2 < NC && tid == 0) expect_tx(mbar, CHUNK_BYTES);

    const uint32_t aBase0 = sbase + A_off(0,b,a_row) + a_koff;
    const uint32_t aBase1 = sbase + A_off(1,b,a_row) + a_koff;
    const uint32_t bcH = sbase + B_off(0,b,b_n)      + b_koff;   // c-half hi
    const uint32_t bhH = sbase + B_off(0,b,b_n + 32) + b_koff;   // h-half hi
    const uint32_t bcL = sbase + B_off(1,b,b_n)      + b_koff;   // c-half lo
    const uint32_t bhL = sbase + B_off(1,b,b_n + 32) + b_koff;   // h-half lo

    #pragma unroll
    for (int kk = 0; kk < KB; kk += 16){
      const uint32_t kb = (uint32_t)(kk*2);
      uint32_t Ah[4], Al[4], BcH[4], BhH[4], BcL[4], BhL[4];
      ldsm4(Ah,  aBase0 + kb);
      ldsm4(Al,  aBase1 + kb);
      ldsm4(BcH, bcH + kb);
      ldsm4(BhH, bhH + kb);
      ldsm4(BcL, bcL + kb);
      ldsm4(BhL, bhL + kb);
      // c-half (nt 0,1), h-half (nt 2,3)
      mma16816(C[0], Ah, BcH[0], BcH[1]);
      mma16816(C[0], Al, BcH[0], BcH[1]);
      mma16816(C[0], Ah, BcL[0], BcL[1]);
      mma16816(C[1], Ah, BcH[2], BcH[3]);
      mma16816(C[1], Al, BcH[2], BcH[3]);
      mma16816(C[1], Ah, BcL[2], BcL[3]);
      mma16816(C[2], Ah, BhH[0], BhH[1]);
      mma16816(C[2], Al, BhH[0], BhH[1]);
      mma16816(C[2], Ah, BhL[0], BhL[1]);
      mma16816(C[3], Ah, BhH[2], BhH[3]);
      mma16816(C[3], Al, BhH[2], BhH[3]);
      mma16816(C[3], Ah, BhL[2], BhL[3]);
    }
    __syncthreads();
    if (c + 2 < NC) load_chunk(c+2, b);
  }

  // fp32 partials: C[nt] (c cols) with C[nt+2] (h cols)
  #pragma unroll
  for (int nt=0; nt<2; nt++){
    int r0 = wm*16 + (lane>>2);
    int gc = j + wn*16 + nt*8 + 2*(lane&3);
    *(float2*)(part + (size_t)r0*2048 + gc)            = make_float2(C[nt][0],   C[nt][1]);
    *(float2*)(part + (size_t)(r0+8)*2048 + gc)        = make_float2(C[nt][2],   C[nt][3]);
    *(float2*)(part + (size_t)r0*2048 + gc + 1024)     = make_float2(C[nt+2][0], C[nt+2][1]);
    *(float2*)(part + (size_t)(r0+8)*2048 + gc + 1024) = make_float2(C[nt+2][2], C[nt+2][3]);
  }
}

__device__ __forceinline__ float* part_ptr(int slice, int slot){
  return g_part[slice*3 + slot];
}

// vectorized gate update over 4 consecutive cols; returns s_next values
__device__ __forceinline__ float4 gate4(float4 c, float4 h, float4 sp, int act){
  float4 r;
  float hv[4] = {h.x, h.y, h.z, h.w};
  float cv[4] = {c.x, c.y, c.z, c.w};
  float sv[4] = {sp.x, sp.y, sp.z, sp.w};
  float rv[4];
  #pragma unroll
  for (int q=0;q<4;q++){
    float gate = 1.f/(1.f + __expf(-cv[q]));
    rv[q] = fmaf(gate, act_fn(act, hv[q]) - sv[q], sv[q]);
  }
  r.x = rv[0]; r.y = rv[1]; r.z = rv[2]; r.w = rv[3];
  return r;
}

__device__ __forceinline__ void store_shadow4(bf16* hi, bf16* lo, int idx, float4 v){
  __nv_bfloat16 h0 = __float2bfloat16(v.x), h1 = __float2bfloat16(v.y);
  __nv_bfloat16 h2 = __float2bfloat16(v.z), h3 = __float2bfloat16(v.w);
  __nv_bfloat162 hp0(h0, h1), hp1(h2, h3);
  *(uint2*)(hi + idx) = make_uint2(*(uint32_t*)&hp0, *(uint32_t*)&hp1);
  __nv_bfloat162 lp0(__float2bfloat16(v.x - __bfloat162float(h0)),
                     __float2bfloat16(v.y - __bfloat162float(h1)));
  __nv_bfloat162 lp1(__float2bfloat16(v.z - __bfloat162float(h2)),
                     __float2bfloat16(v.w - __bfloat162float(h3)));
  *(uint2*)(lo + idx) = make_uint2(*(uint32_t*)&lp0, *(uint32_t*)&lp1);
}

// ---------------- persistent scan kernel ----------------
__global__ void __launch_bounds__(NT,1) rnn_persistent(float* __restrict__ out){
  extern __shared__ __align__(16) unsigned char dsm[];
  __shared__ __align__(8) uint64_t s_mbar[2];

  const int tid = threadIdx.x;
  uint32_t sbase, mb0;
  { uint32_t a; asm("{ .reg .u64 t; cvta.to.shared.u64 t, %1; cvt.u32.u64 %0, t; }" : "=r"(a) : "l"(dsm)); sbase = a; }
  { uint32_t a; asm("{ .reg .u64 t; cvta.to.shared.u64 t, %1; cvt.u32.u64 %0, t; }" : "=r"(a) : "l"(&s_mbar[0])); mb0 = a; }

  if (tid == 0){
    asm volatile("mbarrier.init.shared.b64 [%0], %1;" :: "r"(mb0),   "r"(1u) : "memory");
    asm volatile("mbarrier.init.shared.b64 [%0], %1;" :: "r"(mb0+8), "r"(1u) : "memory");
  }
  __syncthreads();

  int ph[2] = {0,0};
  unsigned target = 0;
  const int Q4 = BB*NH/4;     // 32768 float4 elements per state

  for (int t = 0; t < TT; t++){
    // ---- G0: ch = [x_t | h] @ W0, 8 slices x 32 ntiles ----
    for (int it = blockIdx.x; it < 256; it += gridDim.x){
      int ntile = it >> 3, slice = it & 7;
      int kc0 = slice*KC;
      const bf16 *ah, *al; long astr;
      if (kc0 < 1024){ ah = g_xh + (size_t)t*NI + kc0; al = g_xl + (size_t)t*NI + kc0; astr = (long)TT*NI; }
      else           { ah = g_hh + (kc0-1024);         al = g_hl + (kc0-1024);         astr = NH; }
      gemm_tile(ah, al, astr, g_W0th + kc0, g_W0tl + kc0, 2048,
                part_ptr(slice,0), ntile*32, sbase, mb0, ph, tid);
    }
    gsync(target);
    // ---- E0: s0 = h + sig(c)*(tanh(hh) - h), 8 slices ----
    for (int id = blockIdx.x*NT + tid; id < Q4; id += gridDim.x*NT){
      int row = id >> 8, col = (id & 255)*4;
      float4 c = make_float4(0,0,0,0), h = make_float4(0,0,0,0);
      #pragma unroll
      for (int s=0;s<8;s++){
        const float* p = part_ptr(s,0) + (size_t)row*2048;
        float4 pc = *(const float4*)(p + col);
        float4 ph4 = *(const float4*)(p + 1024 + col);
        c.x+=pc.x; c.y+=pc.y; c.z+=pc.z; c.w+=pc.w;
        h.x+=ph4.x; h.y+=ph4.y; h.z+=ph4.z; h.w+=ph4.w;
      }
      int idx = row*NH + col;
      float4 sp = *(const float4*)(g_hbuf + idx);
      float4 v = gate4(c, h, sp, 3);
      *(float4*)(&g_s[0][idx]) = v;
      store_shadow4(g_sh[0], g_sl[0], idx, v);
    }
    gsync(target);

    // ---- G1: gene0 (s0 @ W[0]), 4 slices x 32 ----
    for (int it = blockIdx.x; it < 128; it += gridDim.x){
      int ntile = it >> 2, slice = it & 3;
      int kc0 = slice*KC;
      gemm_tile(g_sh[0] + kc0, g_sl[0] + kc0, NH,
                g_Wsth[0] + kc0, g_Wstl[0] + kc0, 1024,
                part_ptr(slice,0), ntile*32, sbase, mb0, ph, tid);
    }
    gsync(target);
    // ---- E1: s1 (sigmoid, resid s0), 4 slices ----
    for (int id = blockIdx.x*NT + tid; id < Q4; id += gridDim.x*NT){
      int row = id >> 8, col = (id & 255)*4;
      float4 c = make_float4(0,0,0,0), h = make_float4(0,0,0,0);
      #pragma unroll
      for (int s=0;s<4;s++){
        const float* p = part_ptr(s,0) + (size_t)row*2048;
        float4 pc = *(const float4*)(p + col);
        float4 ph4 = *(const float4*)(p + 1024 + col);
        c.x+=pc.x; c.y+=pc.y; c.z+=pc.z; c.w+=pc.w;
        h.x+=ph4.x; h.y+=ph4.y; h.z+=ph4.z; h.w+=ph4.w;
      }
      int idx = row*NH + col;
      float4 sp = *(const float4*)(&g_s[0][idx]);
      float4 v = gate4(c, h, sp, 0);
      *(float4*)(&g_s[1][idx]) = v;
      store_shadow4(g_sh[1], g_sl[1], idx, v);
    }
    gsync(target);

    // ---- G2: genes 1,2,3 from s1; 3 slots x 32 ntiles x 4 slices ----
    for (int it = blockIdx.x; it < 384; it += gridDim.x){
      int slot = it >> 7, rem = it & 127;
      int ntile = rem >> 2, slice = rem & 3;
      int gi = 1 + slot;
      int kc0 = slice*KC;
      gemm_tile(g_sh[1] + kc0, g_sl[1] + kc0, NH,
                g_Wsth[gi] + kc0, g_Wstl[gi] + kc0, 1024,
                part_ptr(slice,slot), ntile*32, sbase, mb0, ph, tid);
    }
    gsync(target);
    // ---- E2: s2 (relu), s3 (relu), s4 (identity); resid s1 ----
    for (int id = blockIdx.x*NT + tid; id < 3*Q4; id += gridDim.x*NT){
      int slot = id / Q4, rid = id % Q4;
      int row = rid >> 8, col = (rid & 255)*4;
      float4 c = make_float4(0,0,0,0), h = make_float4(0,0,0,0);
      #pragma unroll
      for (int s=0;s<4;s++){
        const float* p = part_ptr(s,slot) + (size_t)row*2048;
        float4 pc = *(const float4*)(p + col);
        float4 ph4 = *(const float4*)(p + 1024 + col);
        c.x+=pc.x; c.y+=pc.y; c.z+=pc.z; c.w+=pc.w;
        h.x+=ph4.x; h.y+=ph4.y; h.z+=ph4.z; h.w+=ph4.w;
      }
      int idx = row*NH + col;
      float4 sp = *(const float4*)(&g_s[1][idx]);
      float4 v = gate4(c, h, sp, (slot==2)?2:1);
      int dst = slot + 2;
      *(float4*)(&g_s[dst][idx]) = v;
      if (dst < 4) store_shadow4(g_sh[dst], g_sl[dst], idx, v);
    }
    gsync(target);

    // ---- G3: gene4 (s2) slot0, gene6 (s3) slot1 ----
    for (int it = blockIdx.x; it < 256; it += gridDim.x){
      int slot = it >> 7, rem = it & 127;
      int ntile = rem >> 2, slice = rem & 3;
      int gi = 4 + slot*2;
      int src = 2 + slot;
      int kc0 = slice*KC;
      gemm_tile(g_sh[src] + kc0, g_sl[src] + kc0, NH,
                g_Wsth[gi] + kc0, g_Wstl[gi] + kc0, 1024,
                part_ptr(slice,slot), ntile*32, sbase, mb0, ph, tid);
    }
    gsync(target);
    // ---- E3: s5 (tanh, resid s2), s7 (tanh, resid s3) ----
    for (int id = blockIdx.x*NT + tid; id < 2*Q4; id += gridDim.x*NT){
      int slot = id / Q4, rid = id % Q4;
      int row = rid >> 8, col = (rid & 255)*4;
      float4 c = make_float4(0,0,0,0), h = make_float4(0,0,0,0);
      #pragma unroll
      for (int s=0;s<4;s++){
        const float* p = part_ptr(s,slot) + (size_t)row*2048;
        float4 pc = *(const float4*)(p + col);
        float4 ph4 = *(const float4*)(p + 1024 + col);
        c.x+=pc.x; c.y+=pc.y; c.z+=pc.z; c.w+=pc.w;
        h.x+=ph4.x; h.y+=ph4.y; h.z+=ph4.z; h.w+=ph4.w;
      }
      int idx = row*NH + col;
      float4 sp = *(const float4*)(&g_s[2+slot][idx]);
      float4 v = gate4(c, h, sp, 3);
      int dst = (slot==0) ? 5 : 7;
      *(float4*)(&g_s[dst][idx]) = v;
      if (dst == 5) store_shadow4(g_sh[5], g_sl[5], idx, v);
    }
    gsync(target);

    // ---- G4: gene5 slot0, gene7 slot1, both from s5 ----
    for (int it = blockIdx.x; it < 256; it += gridDim.x){
      int slot = it >> 7, rem = it & 127;
      int ntile = rem >> 2, slice = rem & 3;
      int gi = 5 + slot*2;
      int kc0 = slice*KC;
      gemm_tile(g_sh[5] + kc0, g_sl[5] + kc0, NH,
                g_Wsth[gi] + kc0, g_Wstl[gi] + kc0, 1024,
                part_ptr(slice,slot), ntile*32, sbase, mb0, ph, tid);
    }
    gsync(target);
    // ---- E4 + finalize: s6 (sig), s8 (relu), resid s5; h = mean(s1..s8) ----
    for (int id = blockIdx.x*NT + tid; id < Q4; id += gridDim.x*NT){
      int row = id >> 8, col = (id & 255)*4;
      float4 c6 = make_float4(0,0,0,0), h6 = make_float4(0,0,0,0);
      float4 c8 = make_float4(0,0,0,0), h8 = make_float4(0,0,0,0);
      #pragma unroll
      for (int s=0;s<4;s++){
        const float* p0 = part_ptr(s,0) + (size_t)row*2048;
        const float* p1 = part_ptr(s,1) + (size_t)row*2048;
        float4 a0 = *(const float4*)(p0 + col), b0 = *(const float4*)(p0 + 1024 + col);
        float4 a1 = *(const float4*)(p1 + col), b1 = *(const float4*)(p1 + 1024 + col);
        c6.x+=a0.x; c6.y+=a0.y; c6.z+=a0.z; c6.w+=a0.w;
        h6.x+=b0.x; h6.y+=b0.y; h6.z+=b0.z; h6.w+=b0.w;
        c8.x+=a1.x; c8.y+=a1.y; c8.z+=a1.z; c8.w+=a1.w;
        h8.x+=b1.x; h8.y+=b1.y; h8.z+=b1.z; h8.w+=b1.w;
      }
      int idx = row*NH + col;
      float4 s5v = *(const float4*)(&g_s[5][idx]);
      float4 s6v = gate4(c6, h6, s5v, 0);
      float4 s8v = gate4(c8, h8, s5v, 1);
      float4 s1v = *(const float4*)(&g_s[1][idx]);
      float4 s2v = *(const float4*)(&g_s[2][idx]);
      float4 s3v = *(const float4*)(&g_s[3][idx]);
      float4 s4v = *(const float4*)(&g_s[4][idx]);
      float4 s7v = *(const float4*)(&g_s[7][idx]);
      float4 m;
      m.x = (s1v.x+s2v.x+s3v.x+s4v.x+s5v.x+s6v.x+s7v.x+s8v.x)*0.125f;
      m.y = (s1v.y+s2v.y+s3v.y+s4v.y+s5v.y+s6v.y+s7v.y+s8v.y)*0.125f;
      m.z = (s1v.z+s2v.z+s3v.z+s4v.z+s5v.z+s6v.z+s7v.z+s8v.z)*0.125f;
      m.w = (s1v.w+s2v.w+s3v.w+s4v.w+s5v.w+s6v.w+s7v.w+s8v.w)*0.125f;
      *(float4*)(&g_hbuf[idx]) = m;
      store_shadow4(g_hh, g_hl, idx, m);
      *(float4*)(&out[((size_t)row*TT + t)*NH + col]) = m;
      if (t == TT-1) *(float4*)(&out[(size_t)BB*TT*NH + idx]) = m;
    }
    gsync(target);
  }
}

// ---------------- prologue helpers ----------------
__global__ void split_kernel(const float* __restrict__ src, bf16* __restrict__ hi,
                             bf16* __restrict__ lo, float* __restrict__ fcopy, int n){
  int i = blockIdx.x*blockDim.x + threadIdx.x;
  int stride = gridDim.x*blockDim.x;
  for (; i < n; i += stride){
    float v = src[i];
    bf16 h = __float2bfloat16(v);
    hi[i] = h;
    lo[i] = __float2bfloat16(v - __bfloat162float(h));
    if (fcopy) fcopy[i] = v;
  }
}

// transpose + hi/lo split: in [K][N] fp32 -> out [N][K] bf16 x2
__global__ void tsplit_kernel(const float* __restrict__ in, bf16* __restrict__ outh,
                              bf16* __restrict__ outl, int K, int N){
  __shared__ float tile[32][33];
  const float* src = in + (size_t)blockIdx.z*K*N;
  bf16* oh = outh + (size_t)blockIdx.z*N*K;
  bf16* ol = outl + (size_t)blockIdx.z*N*K;
  int tx = threadIdx.x, ty = threadIdx.y;
  int n0 = blockIdx.x*32, k0 = blockIdx.y*32;
  #pragma unroll
  for (int r=0;r<4;r++)
    tile[ty + r*8][tx] = src[(size_t)(k0 + ty + r*8)*N + n0 + tx];
  __syncthreads();
  #pragma unroll
  for (int r=0;r<4;r++){
    float v = tile[tx][ty + r*8];
    size_t o = (size_t)(n0 + ty + r*8)*K + k0 + tx;
    bf16 h = __float2bfloat16(v);
    oh[o] = h;
    ol[o] = __float2bfloat16(v - __bfloat162float(h));
  }
}

__global__ void reset_kernel(){ g_arrive = 0; g_epoch = 0; }

// ---------------- host launch ----------------
extern "C" void kernel_launch(void* const* d_in, const int* in_sizes, int n_in,
                              void* d_out, int out_size){
  const float *x=nullptr, *h0=nullptr, *W0=nullptr, *Ws=nullptr;
  for (int i=0;i<n_in;i++){
    long n = in_sizes[i];
    if      (n == (long)BB*TT*NI)   x  = (const float*)d_in[i];
    else if (n == (long)BB*NH)      h0 = (const float*)d_in[i];
    else if (n == (long)2048*2048)  W0 = (const float*)d_in[i];
    else if (n == (long)8*NH*2048)  Ws = (const float*)d_in[i];
  }
  if (!x || !h0 || !W0 || !Ws) return;
  float* out = (float*)d_out;

  void* p;
  cudaGetSymbolAddress(&p, g_hbuf); float* h_p  = (float*)p;
  cudaGetSymbolAddress(&p, g_hh);   bf16*  hh_p = (bf16*)p;
  cudaGetSymbolAddress(&p, g_hl);   bf16*  hl_p = (bf16*)p;
  cudaGetSymbolAddress(&p, g_xh);   bf16*  xh_p = (bf16*)p;
  cudaGetSymbolAddress(&p, g_xl);   bf16*  xl_p = (bf16*)p;
  cudaGetSymbolAddress(&p, g_W0th); bf16*  w0h_p= (bf16*)p;
  cudaGetSymbolAddress(&p, g_W0tl); bf16*  w0l_p= (bf16*)p;
  cudaGetSymbolAddress(&p, g_Wsth); bf16*  wsh_p= (bf16*)p;
  cudaGetSymbolAddress(&p, g_Wstl); bf16*  wsl_p= (bf16*)p;

  cudaFuncSetAttribute(rnn_persistent, cudaFuncAttributeMaxDynamicSharedMemorySize, SMEM_DYN);

  int dev = 0, nsm = 0;
  cudaGetDevice(&dev);
  cudaDeviceGetAttribute(&nsm, cudaDevAttrMultiProcessorCount, dev);

  // prologue: transpose+split weights (hi+lo), split inputs and initial hidden
  tsplit_kernel<<<dim3(64,64,1), dim3(32,8)>>>(W0, w0h_p, w0l_p, 2048, 2048);
  tsplit_kernel<<<dim3(64,32,8), dim3(32,8)>>>(Ws, wsh_p, wsl_p, 1024, 2048);
  split_kernel<<<8192,256>>>(x, xh_p, xl_p, nullptr, BB*TT*NI);
  split_kernel<<<512,256>>>(h0, hh_p, hl_p, h_p, BB*NH);
  reset_kernel<<<1,1>>>();

  rnn_persistent<<<nsm, NT, SMEM_DYN>>>(out);
  (void)out_size;
}

// round 7
// speedup vs baseline: 1.6447x; 1.6447x over previous
#include <cuda_runtime.h>
#include <cuda_fp16.h>
#include <cstdint>

#define BB   128
#define TT   256
#define NH   1024
#define NI   1024
#define NT   256               // 8 warps
#define KBW  256               // k elems per chunk
#define ROWB 528               // smem row bytes (512 + 16 pad, LDSM conflict-free)
#define STAGE_BYTES (64*ROWB)  // 33792 per region per stage
#define AREG (3*STAGE_BYTES)   // A region total (3 stages)
#define SMEM_DYN (2*AREG)      // 202752 bytes
#define CHUNK_TX 65536u        // (64 A rows + 64 W rows) * 512 B

// ---------------- device scratch ----------------
__device__ __align__(16) float  g_s [9][BB*NH];     // fp32 states s0..s8
__device__ __align__(16) __half g_sf[6][BB*NH];     // fp16 states (idx 0,1,2,3,5 used)
__device__ __align__(16) float  g_hbuf[BB*NH];
__device__ __align__(16) __half g_hf[BB*NH];
__device__ __align__(16) __half g_xf[BB*TT*NI];
__device__ __align__(16) __half g_W0t[2048*2048];   // [n][k] fp16, transposed
__device__ __align__(16) __half g_Wst[8][2048*1024];// [n][k] fp16 per gene
__device__ unsigned g_arrive, g_epoch;

// ---------------- primitives ----------------
__device__ __forceinline__ void mma16816(float c[4], const uint32_t a[4],
                                         uint32_t b0, uint32_t b1){
  asm volatile(
    "mma.sync.aligned.m16n8k16.row.col.f32.f16.f16.f32 "
    "{%0,%1,%2,%3},{%4,%5,%6,%7},{%8,%9},{%0,%1,%2,%3};\n"
    : "+f"(c[0]), "+f"(c[1]), "+f"(c[2]), "+f"(c[3])
    : "r"(a[0]), "r"(a[1]), "r"(a[2]), "r"(a[3]), "r"(b0), "r"(b1));
}

__device__ __forceinline__ void ldsm4(uint32_t r[4], uint32_t addr){
  asm volatile("ldmatrix.sync.aligned.m8n8.x4.shared.b16 {%0,%1,%2,%3}, [%4];"
    : "=r"(r[0]), "=r"(r[1]), "=r"(r[2]), "=r"(r[3]) : "r"(addr));
}

__device__ __forceinline__ void bulk512(uint32_t dst, const void* src, uint32_t mbar){
  asm volatile(
    "cp.async.bulk.shared::cta.global.mbarrier::complete_tx::bytes [%0], [%1], %2, [%3];"
    :: "r"(dst), "l"(src), "r"(512u), "r"(mbar) : "memory");
}

__device__ __forceinline__ void expect_tx(uint32_t mbar, uint32_t bytes){
  asm volatile("mbarrier.arrive.expect_tx.shared.b64 _, [%0], %1;"
    :: "r"(mbar), "r"(bytes) : "memory");
}

__device__ __forceinline__ void mbar_wait(uint32_t mbar, int phase){
  uint32_t done;
  asm volatile(
    "{\n\t.reg .pred p;\n\t"
    "mbarrier.try_wait.parity.acquire.cta.shared::cta.b64 p, [%1], %2;\n\t"
    "selp.b32 %0, 1, 0, p;\n\t}"
    : "=r"(done) : "r"(mbar), "r"((uint32_t)phase) : "memory");
  if (!done){
    asm volatile(
      "{\n\t.reg .pred P1;\n\t"
      "WAIT_LOOP_%=:\n\t"
      "mbarrier.try_wait.parity.acquire.cta.shared::cta.b64 P1, [%0], %1, 0x989680;\n\t"
      "@P1 bra.uni WAIT_DONE_%=;\n\t"
      "bra.uni WAIT_LOOP_%=;\n\t"
      "WAIT_DONE_%=:\n\t}"
      :: "r"(mbar), "r"((uint32_t)phase) : "memory");
  }
}

__device__ __forceinline__ void gsync(unsigned &target){
  __syncthreads();
  if (threadIdx.x == 0){
    target += gridDim.x;
    unsigned old;
    asm volatile("atom.add.release.gpu.global.u32 %0, [%1], %2;"
                 : "=r"(old) : "l"(&g_arrive), "r"(1u) : "memory");
    if (old + 1 == target){
      asm volatile("st.release.gpu.global.u32 [%0], %1;" :: "l"(&g_epoch), "r"(target) : "memory");
    } else {
      unsigned e; int spins = 0;
      do {
        asm volatile("ld.acquire.gpu.global.u32 %0, [%1];" : "=r"(e) : "l"(&g_epoch) : "memory");
        if (++spins > 32) __nanosleep(64);
      } while ((int)(e - target) < 0);
    }
  }
  __syncthreads();
}

__device__ __forceinline__ float act_fn(int act, float v){
  switch (act){
    case 0:  return 1.f/(1.f + __expf(-v));
    case 1:  return fmaxf(v, 0.f);
    case 2:  return v;
    default: return tanhf(v);
  }
}

__device__ __forceinline__ uint32_t A_off(int st, int row){
  return (uint32_t)(st*STAGE_BYTES + row*ROWB);
}
__device__ __forceinline__ uint32_t W_off(int st, int row){
  return (uint32_t)(AREG + st*STAGE_BYTES + row*ROWB);
}

// ---------------- full-K GEMM job (fp16 single-term) ----------------
// M=64 rows [m0,m0+64), 32 c-cols [j,j+32) paired with 32 h-cols [1024+j,...).
// C accumulated in registers across all K -> fused gate epilogue, no partials.
// 8 warps as 4(M)x2(N): warp = 16 rows x (16c+16h), c/h pair in same thread.
// a2 non-null => A source switches to a2 (stride NH) for k >= 1024 (G0).
__device__ void job(
    const __half* __restrict__ a1, long a1s, const __half* __restrict__ a2,
    const __half* __restrict__ wt, int Kw,
    const float* __restrict__ resid,
    float* __restrict__ outS, __half* __restrict__ outH,
    int m0, int j, int act, int NC,
    uint32_t sbase, uint32_t mb0, int ph[3], int tid)
{
  const int lane = tid & 31, warp = tid >> 5;
  const int wm = warp >> 1, wn = warp & 1;

  float C[4][4];
  #pragma unroll
  for (int n=0;n<4;n++)
    #pragma unroll
    for (int q=0;q<4;q++) C[n][q]=0.f;

  auto load_chunk = [&](int c, int st){
    if (tid < 128){
      int k0 = c*KBW;
      uint32_t mbar = mb0 + st*8;
      if (tid < 64){
        int row = tid;
        const __half* src;
        if (a2 && k0 >= 1024) src = a2 + (size_t)(m0+row)*NH + (k0-1024);
        else                  src = a1 + (size_t)(m0+row)*a1s + k0;
        bulk512(sbase + A_off(st,row), src, mbar);
      } else {
        int n = tid - 64;
        int gcol = (n < 32) ? (j + n) : (NH + j + (n - 32));
        bulk512(sbase + W_off(st,n), wt + (size_t)gcol*Kw + k0, mbar);
      }
    }
  };

  // prologue: arm + load 3 stages (NC >= 4 always)
  if (tid == 0){
    expect_tx(mb0,    CHUNK_TX);
    expect_tx(mb0+8,  CHUNK_TX);
    expect_tx(mb0+16, CHUNK_TX);
  }
  __syncthreads();
  load_chunk(0,0); load_chunk(1,1); load_chunk(2,2);

  // per-lane LDSM addresses
  const uint32_t a_row  = (uint32_t)(wm*16 + (lane & 15));
  const uint32_t a_koff = (uint32_t)((lane >> 4) * 16);
  const int sub = lane >> 3;
  const uint32_t b_n    = (uint32_t)(wn*16 + ((sub >> 1) << 3) + (lane & 7));
  const uint32_t b_koff = (uint32_t)((sub & 1) * 16);

  for (int c=0; c<NC; c++){
    const int st = c % 3;
    const uint32_t mbar = mb0 + st*8;
    mbar_wait(mbar, ph[st]); ph[st] ^= 1;
    if (c + 3 < NC && tid == 0) expect_tx(mbar, CHUNK_TX);

    const uint32_t aB = sbase + A_off(st, a_row)      + a_koff;
    const uint32_t cB = sbase + W_off(st, b_n)        + b_koff;
    const uint32_t hB = sbase + W_off(st, b_n + 32)   + b_koff;

    #pragma unroll
    for (int kk = 0; kk < KBW; kk += 16){
      const uint32_t kb = (uint32_t)(kk*2);
      uint32_t A4[4], Bc[4], Bh[4];
      ldsm4(A4, aB + kb);
      ldsm4(Bc, cB + kb);
      ldsm4(Bh, hB + kb);
      mma16816(C[0], A4, Bc[0], Bc[1]);
      mma16816(C[1], A4, Bc[2], Bc[3]);
      mma16816(C[2], A4, Bh[0], Bh[1]);
      mma16816(C[3], A4, Bh[2], Bh[3]);
    }
    __syncthreads();
    if (c + 3 < NC) load_chunk(c+3, st);
  }

  // fused gate epilogue: s = sp + sigmoid(c)*(act(h) - sp)
  #pragma unroll
  for (int nt=0; nt<2; nt++){
    int r0 = wm*16 + (lane>>2);
    int gc = j + wn*16 + nt*8 + 2*(lane&3);
    #pragma unroll
    for (int half=0; half<2; half++){
      int row = m0 + r0 + half*8;
      int q0 = half*2;
      float cv0 = C[nt][q0],   cv1 = C[nt][q0+1];
      float hv0 = C[nt+2][q0], hv1 = C[nt+2][q0+1];
      int idx = row*NH + gc;
      float sp0 = __ldcg(resid + idx), sp1 = __ldcg(resid + idx + 1);
      float g0 = 1.f/(1.f + __expf(-cv0));
      float g1 = 1.f/(1.f + __expf(-cv1));
      float v0 = fmaf(g0, act_fn(act, hv0) - sp0, sp0);
      float v1 = fmaf(g1, act_fn(act, hv1) - sp1, sp1);
      *(float2*)(outS + idx) = make_float2(v0, v1);
      if (outH){
        __half2 hv = __floats2half2_rn(v0, v1);
        *(__half2*)(outH + idx) = hv;
      }
    }
  }
}

// ---------------- persistent scan kernel ----------------
__global__ void __launch_bounds__(NT,1) rnn_persistent(float* __restrict__ out){
  extern __shared__ __align__(16) unsigned char dsm[];
  __shared__ __align__(8) uint64_t s_mbar[3];

  const int tid = threadIdx.x;
  uint32_t sbase, mb0;
  { uint32_t a; asm("{ .reg .u64 t; cvta.to.shared.u64 t, %1; cvt.u32.u64 %0, t; }" : "=r"(a) : "l"(dsm)); sbase = a; }
  { uint32_t a; asm("{ .reg .u64 t; cvta.to.shared.u64 t, %1; cvt.u32.u64 %0, t; }" : "=r"(a) : "l"(&s_mbar[0])); mb0 = a; }

  if (tid == 0){
    #pragma unroll
    for (int b=0;b<3;b++)
      asm volatile("mbarrier.init.shared.b64 [%0], %1;" :: "r"(mb0+b*8), "r"(1u) : "memory");
  }
  __syncthreads();

  int ph[3] = {0,0,0};
  unsigned target = 0;
  const int Q4 = BB*NH/4;

  for (int t = 0; t < TT; t++){
    // G0: [x_t | h] @ W0 -> s0 (tanh, resid h). 64 jobs, K=2048 (8 chunks)
    for (int it = blockIdx.x; it < 64; it += gridDim.x){
      int m0 = (it >> 5)*64, j = (it & 31)*32;
      job(g_xf + (size_t)t*NI, (long)TT*NI, g_hf,
          g_W0t, 2048, g_hbuf, g_s[0], g_sf[0],
          m0, j, 3, 8, sbase, mb0, ph, tid);
    }
    gsync(target);

    // G1: gene0 (sigmoid) s0 -> s1. 64 jobs, K=1024
    for (int it = blockIdx.x; it < 64; it += gridDim.x){
      int m0 = (it >> 5)*64, j = (it & 31)*32;
      job(g_sf[0], NH, nullptr, g_Wst[0], 1024,
          g_s[0], g_s[1], g_sf[1], m0, j, 0, 4, sbase, mb0, ph, tid);
    }
    gsync(target);

    // G2: genes 1,2,3 from s1 -> s2(relu), s3(relu), s4(identity). 192 jobs
    for (int it = blockIdx.x; it < 192; it += gridDim.x){
      int slot = it / 64, rem = it % 64;
      int m0 = (rem >> 5)*64, j = (rem & 31)*32;
      int gi = 1 + slot, dst = 2 + slot;
      job(g_sf[1], NH, nullptr, g_Wst[gi], 1024,
          g_s[1], g_s[dst], (dst < 4) ? g_sf[dst] : (__half*)nullptr,
          m0, j, (slot==2)?2:1, 4, sbase, mb0, ph, tid);
    }
    gsync(target);

    // G3: gene4 (tanh) s2->s5 ; gene6 (tanh) s3->s7. 128 jobs
    for (int it = blockIdx.x; it < 128; it += gridDim.x){
      int slot = it >> 6, rem = it & 63;
      int m0 = (rem >> 5)*64, j = (rem & 31)*32;
      int gi = 4 + slot*2, src = 2 + slot, dst = gi + 1;   // 5 or 7
      job(g_sf[src], NH, nullptr, g_Wst[gi], 1024,
          g_s[src], g_s[dst], (dst==5) ? g_sf[5] : (__half*)nullptr,
          m0, j, 3, 4, sbase, mb0, ph, tid);
    }
    gsync(target);

    // G4: gene5 (sigmoid) s5->s6 ; gene7 (relu) s5->s8. 128 jobs
    for (int it = blockIdx.x; it < 128; it += gridDim.x){
      int slot = it >> 6, rem = it & 63;
      int m0 = (rem >> 5)*64, j = (rem & 31)*32;
      int gi = 5 + slot*2, dst = gi + 1;                   // 6 or 8
      job(g_sf[5], NH, nullptr, g_Wst[gi], 1024,
          g_s[5], g_s[dst], (__half*)nullptr,
          m0, j, (slot==0)?0:1, 4, sbase, mb0, ph, tid);
    }
    gsync(target);

    // F: h = mean(s1..s8); emit hiddens[b,t,:]; fp16 copy of h
    for (int id = blockIdx.x*NT + tid; id < Q4; id += gridDim.x*NT){
      int row = id >> 8, col = (id & 255)*4;
      int idx = row*NH + col;
      float4 m = make_float4(0,0,0,0);
      #pragma unroll
      for (int k=1;k<9;k++){
        float4 v = *(const float4*)(&g_s[k][idx]);
        m.x += v.x; m.y += v.y; m.z += v.z; m.w += v.w;
      }
      m.x *= 0.125f; m.y *= 0.125f; m.z *= 0.125f; m.w *= 0.125f;
      *(float4*)(&g_hbuf[idx]) = m;
      __half2 h0 = __floats2half2_rn(m.x, m.y);
      __half2 h1 = __floats2half2_rn(m.z, m.w);
      *(uint2*)(&g_hf[idx]) = make_uint2(*(uint32_t*)&h0, *(uint32_t*)&h1);
      *(float4*)(&out[((size_t)row*TT + t)*NH + col]) = m;
      if (t == TT-1) *(float4*)(&out[(size_t)BB*TT*NH + idx]) = m;
    }
    gsync(target);
  }
}

// ---------------- prologue helpers ----------------
__global__ void tohalf_kernel(const float* __restrict__ src, __half* __restrict__ dst,
                              float* __restrict__ fcopy, int n){
  int i = blockIdx.x*blockDim.x + threadIdx.x;
  int stride = gridDim.x*blockDim.x;
  for (; i < n; i += stride){
    float v = src[i];
    dst[i] = __float2half_rn(v);
    if (fcopy) fcopy[i] = v;
  }
}

// transpose to fp16: in [K][N] fp32 -> out [N][K] half. One z-slice per gene.
__global__ void thalf_kernel(const float* __restrict__ in, __half* __restrict__ outh,
                             int K, int N){
  __shared__ float tile[32][33];
  const float* src = in + (size_t)blockIdx.z*K*N;
  __half* oh = outh + (size_t)blockIdx.z*N*K;
  int tx = threadIdx.x, ty = threadIdx.y;
  int n0 = blockIdx.x*32, k0 = blockIdx.y*32;
  #pragma unroll
  for (int r=0;r<4;r++)
    tile[ty + r*8][tx] = src[(size_t)(k0 + ty + r*8)*N + n0 + tx];
  __syncthreads();
  #pragma unroll
  for (int r=0;r<4;r++)
    oh[(size_t)(n0 + ty + r*8)*K + k0 + tx] = __float2half_rn(tile[tx][ty + r*8]);
}

__global__ void reset_kernel(){ g_arrive = 0; g_epoch = 0; }

// ---------------- host launch ----------------
extern "C" void kernel_launch(void* const* d_in, const int* in_sizes, int n_in,
                              void* d_out, int out_size){
  const float *x=nullptr, *h0=nullptr, *W0=nullptr, *Ws=nullptr;
  for (int i=0;i<n_in;i++){
    long n = in_sizes[i];
    if      (n == (long)BB*TT*NI)   x  = (const float*)d_in[i];
    else if (n == (long)BB*NH)      h0 = (const float*)d_in[i];
    else if (n == (long)2048*2048)  W0 = (const float*)d_in[i];
    else if (n == (long)8*NH*2048)  Ws = (const float*)d_in[i];
  }
  if (!x || !h0 || !W0 || !Ws) return;
  float* out = (float*)d_out;

  void* p;
  cudaGetSymbolAddress(&p, g_hbuf); float*  h_p  = (float*)p;
  cudaGetSymbolAddress(&p, g_hf);   __half* hf_p = (__half*)p;
  cudaGetSymbolAddress(&p, g_xf);   __half* xf_p = (__half*)p;
  cudaGetSymbolAddress(&p, g_W0t);  __half* w0_p = (__half*)p;
  cudaGetSymbolAddress(&p, g_Wst);  __half* ws_p = (__half*)p;

  cudaFuncSetAttribute(rnn_persistent, cudaFuncAttributeMaxDynamicSharedMemorySize, SMEM_DYN);

  int dev = 0, nsm = 0;
  cudaGetDevice(&dev);
  cudaDeviceGetAttribute(&nsm, cudaDevAttrMultiProcessorCount, dev);

  // prologue: transpose weights to fp16 [n][k], convert x and h0
  thalf_kernel<<<dim3(64,64,1), dim3(32,8)>>>(W0, w0_p, 2048, 2048);
  thalf_kernel<<<dim3(64,32,8), dim3(32,8)>>>(Ws, ws_p, 1024, 2048);
  tohalf_kernel<<<8192,256>>>(x, xf_p, nullptr, BB*TT*NI);
  tohalf_kernel<<<512,256>>>(h0, hf_p, h_p, BB*NH);
  reset_kernel<<<1,1>>>();

  rnn_persistent<<<nsm, NT, SMEM_DYN>>>(out);
  (void)out_size;
}

// round 8
// speedup vs baseline: 1.6592x; 1.0089x over previous
#include <cuda_runtime.h>
#include <cuda_fp16.h>
#include <cstdint>

#define BB   128
#define TT   256
#define NH   1024
#define NI   1024
#define NT   256               // 8 warps
#define KBW  256               // k elems per chunk
#define ROWB 528               // smem row bytes (512 + 16 pad, LDSM conflict-free)
#define STAGE_BYTES (64*ROWB)
#define AREG (3*STAGE_BYTES)
#define SMEM_DYN (2*AREG)      // 202752 bytes
#define TX_STD   49152u        // (64 A + 32 W) rows * 512 B
#define TX_FUSED 65536u        // (64 A + 64 W) rows * 512 B

// ---------------- device scratch ----------------
__device__ __align__(16) float  g_s [8][BB*NH];     // fp32 states s0..s7 (s6/s8 never stored)
__device__ __align__(16) __half g_sf[6][BB*NH];     // fp16 states (0,1,2,3,5 used)
__device__ __align__(16) float  g_hbuf[BB*NH];
__device__ __align__(16) __half g_hf[BB*NH];
__device__ __align__(16) __half g_xf[BB*TT*NI];
__device__ __align__(16) __half g_W0t[2048*2048];   // [n][k] fp16, transposed
__device__ __align__(16) __half g_Wst[8][2048*1024];// [n][k] fp16 per gene
__device__ unsigned g_arrive, g_epoch;

// ---------------- primitives ----------------
__device__ __forceinline__ void mma16816(float c[4], const uint32_t a[4],
                                         uint32_t b0, uint32_t b1){
  asm volatile(
    "mma.sync.aligned.m16n8k16.row.col.f32.f16.f16.f32 "
    "{%0,%1,%2,%3},{%4,%5,%6,%7},{%8,%9},{%0,%1,%2,%3};\n"
    : "+f"(c[0]), "+f"(c[1]), "+f"(c[2]), "+f"(c[3])
    : "r"(a[0]), "r"(a[1]), "r"(a[2]), "r"(a[3]), "r"(b0), "r"(b1));
}

__device__ __forceinline__ void ldsm4(uint32_t r[4], uint32_t addr){
  asm volatile("ldmatrix.sync.aligned.m8n8.x4.shared.b16 {%0,%1,%2,%3}, [%4];"
    : "=r"(r[0]), "=r"(r[1]), "=r"(r[2]), "=r"(r[3]) : "r"(addr));
}

__device__ __forceinline__ void bulk512(uint32_t dst, const void* src, uint32_t mbar){
  asm volatile(
    "cp.async.bulk.shared::cta.global.mbarrier::complete_tx::bytes [%0], [%1], %2, [%3];"
    :: "r"(dst), "l"(src), "r"(512u), "r"(mbar) : "memory");
}

__device__ __forceinline__ void expect_tx(uint32_t mbar, uint32_t bytes){
  asm volatile("mbarrier.arrive.expect_tx.shared.b64 _, [%0], %1;"
    :: "r"(mbar), "r"(bytes) : "memory");
}

__device__ __forceinline__ void mbar_wait(uint32_t mbar, int phase){
  uint32_t done;
  asm volatile(
    "{\n\t.reg .pred p;\n\t"
    "mbarrier.try_wait.parity.acquire.cta.shared::cta.b64 p, [%1], %2;\n\t"
    "selp.b32 %0, 1, 0, p;\n\t}"
    : "=r"(done) : "r"(mbar), "r"((uint32_t)phase) : "memory");
  if (!done){
    asm volatile(
      "{\n\t.reg .pred P1;\n\t"
      "WAIT_LOOP_%=:\n\t"
      "mbarrier.try_wait.parity.acquire.cta.shared::cta.b64 P1, [%0], %1, 0x989680;\n\t"
      "@P1 bra.uni WAIT_DONE_%=;\n\t"
      "bra.uni WAIT_LOOP_%=;\n\t"
      "WAIT_DONE_%=:\n\t}"
      :: "r"(mbar), "r"((uint32_t)phase) : "memory");
  }
}

__device__ __forceinline__ void gsync(unsigned &target){
  __syncthreads();
  if (threadIdx.x == 0){
    target += gridDim.x;
    unsigned old;
    asm volatile("atom.add.release.gpu.global.u32 %0, [%1], %2;"
                 : "=r"(old) : "l"(&g_arrive), "r"(1u) : "memory");
    if (old + 1 == target){
      asm volatile("st.release.gpu.global.u32 [%0], %1;" :: "l"(&g_epoch), "r"(target) : "memory");
    } else {
      unsigned e; int spins = 0;
      do {
        asm volatile("ld.acquire.gpu.global.u32 %0, [%1];" : "=r"(e) : "l"(&g_epoch) : "memory");
        if (++spins > 32) __nanosleep(64);
      } while ((int)(e - target) < 0);
    }
  }
  __syncthreads();
}

__device__ __forceinline__ float act_fn(int act, float v){
  switch (act){
    case 0:  return 1.f/(1.f + __expf(-v));
    case 1:  return fmaxf(v, 0.f);
    case 2:  return v;
    default: return tanhf(v);
  }
}

__device__ __forceinline__ uint32_t A_off(int st, int row){
  return (uint32_t)(st*STAGE_BYTES + row*ROWB);
}
__device__ __forceinline__ uint32_t W_off(int st, int row){
  return (uint32_t)(AREG + st*STAGE_BYTES + row*ROWB);
}

// W smem row layout (32 rows per gene block, interleaved per warp):
// row r: block=r>>4 (warp wn), q=r&15: q<8 -> c-col j0+block*8+q ; q>=8 -> h-col (+1024)
__device__ __forceinline__ int w_gcol(int r, int j0){
  int block = r >> 4, q = r & 15;
  int col = j0 + block*8 + (q & 7);
  return ((q >> 3) ? NH : 0) + col;
}

// ---------------- full-K GEMM job (fp16, fused gate epilogue) ----------------
// M=64 rows [m0,m0+64), 16 c-cols [j0,j0+16) paired with 16 h-cols [1024+j0,...).
// FUSED: two weight sets (gene5+gene7) on the same tile; epilogue computes s6,s8
// locally and finishes the step (mean + output writes) -> no F phase.
// 8 warps as 4(M)x2(N): warp = 16 rows x (8c+8h per gene).
template<bool FUSED>
__device__ void job(
    const __half* __restrict__ a1, long a1s, const __half* __restrict__ a2,
    const __half* __restrict__ wt, const __half* __restrict__ wt2, int Kw,
    const float* __restrict__ resid,
    float* __restrict__ outS, __half* __restrict__ outH,
    int m0, int j0, int act, int NC,
    uint32_t sbase, uint32_t mb0, int ph[3], int tid,
    float* __restrict__ out, int t)
{
  const int lane = tid & 31, warp = tid >> 5;
  const int wm = warp >> 1, wn = warp & 1;
  const uint32_t TX = FUSED ? TX_FUSED : TX_STD;

  float C[FUSED?4:2][4];
  #pragma unroll
  for (int n=0;n<(FUSED?4:2);n++)
    #pragma unroll
    for (int q=0;q<4;q++) C[n][q]=0.f;

  auto load_chunk = [&](int c, int st){
    int k0 = c*KBW;
    uint32_t mbar = mb0 + st*8;
    if (tid < 64){
      int row = tid;
      const __half* src;
      if (a2 && k0 >= 1024) src = a2 + (size_t)(m0+row)*NH + (k0-1024);
      else                  src = a1 + (size_t)(m0+row)*a1s + k0;
      bulk512(sbase + A_off(st,row), src, mbar);
    } else if (tid < (FUSED ? 128 : 96)){
      int n = tid - 64;
      const __half* w = wt;
      int r = n;
      if (FUSED && n >= 32){ w = wt2; r = n - 32; }
      bulk512(sbase + W_off(st,n), w + (size_t)w_gcol(r,j0)*Kw + k0, mbar);
    }
  };

  if (tid == 0){
    expect_tx(mb0,    TX);
    expect_tx(mb0+8,  TX);
    expect_tx(mb0+16, TX);
  }
  __syncthreads();
  load_chunk(0,0); load_chunk(1,1); load_chunk(2,2);

  const uint32_t a_row  = (uint32_t)(wm*16 + (lane & 15));
  const uint32_t a_koff = (uint32_t)((lane >> 4) * 16);
  const int sub = lane >> 3;
  const uint32_t b_row  = (uint32_t)(wn*16 + ((sub >> 1) << 3) + (lane & 7));
  const uint32_t b_koff = (uint32_t)((sub & 1) * 16);

  for (int c=0; c<NC; c++){
    const int st = c % 3;
    const uint32_t mbar = mb0 + st*8;
    mbar_wait(mbar, ph[st]); ph[st] ^= 1;
    if (c + 3 < NC && tid == 0) expect_tx(mbar, TX);

    const uint32_t aB = sbase + A_off(st, a_row) + a_koff;
    const uint32_t bB = sbase + W_off(st, b_row) + b_koff;

    #pragma unroll
    for (int kk = 0; kk < KBW; kk += 16){
      const uint32_t kb = (uint32_t)(kk*2);
      uint32_t A4[4], B5[4];
      ldsm4(A4, aB + kb);
      ldsm4(B5, bB + kb);
      mma16816(C[0], A4, B5[0], B5[1]);   // c-cols
      mma16816(C[1], A4, B5[2], B5[3]);   // h-cols
      if (FUSED){
        uint32_t B7[4];
        ldsm4(B7, bB + 32*ROWB + kb);
        mma16816(C[2], A4, B7[0], B7[1]);
        mma16816(C[3], A4, B7[2], B7[3]);
      }
    }
    __syncthreads();
    if (c + 3 < NC) load_chunk(c+3, st);
  }

  // epilogue
  const int colb = j0 + wn*8 + 2*(lane&3);
  #pragma unroll
  for (int half=0; half<2; half++){
    const int row = m0 + wm*16 + (lane>>2) + half*8;
    const int q0 = half*2;
    const int idx = row*NH + colb;
    if (!FUSED){
      float sp0 = __ldcg(resid + idx), sp1 = __ldcg(resid + idx + 1);
      float g0 = 1.f/(1.f + __expf(-C[0][q0]));
      float g1 = 1.f/(1.f + __expf(-C[0][q0+1]));
      float v0 = fmaf(g0, act_fn(act, C[1][q0])   - sp0, sp0);
      float v1 = fmaf(g1, act_fn(act, C[1][q0+1]) - sp1, sp1);
      *(float2*)(outS + idx) = make_float2(v0, v1);
      if (outH) *(__half2*)(outH + idx) = __floats2half2_rn(v0, v1);
    } else {
      // gene5 (sigmoid act) -> s6 ; gene7 (relu act) -> s8 ; resid = s5
      float s5v0 = __ldcg(resid + idx), s5v1 = __ldcg(resid + idx + 1);
      float g50 = 1.f/(1.f + __expf(-C[0][q0]));
      float g51 = 1.f/(1.f + __expf(-C[0][q0+1]));
      float s60 = fmaf(g50, 1.f/(1.f + __expf(-C[1][q0]))   - s5v0, s5v0);
      float s61 = fmaf(g51, 1.f/(1.f + __expf(-C[1][q0+1])) - s5v1, s5v1);
      float g70 = 1.f/(1.f + __expf(-C[2][q0]));
      float g71 = 1.f/(1.f + __expf(-C[2][q0+1]));
      float s80 = fmaf(g70, fmaxf(C[3][q0],  0.f) - s5v0, s5v0);
      float s81 = fmaf(g71, fmaxf(C[3][q0+1],0.f) - s5v1, s5v1);
      float2 s1v = *(const float2*)(&g_s[1][idx]);
      float2 s2v = *(const float2*)(&g_s[2][idx]);
      float2 s3v = *(const float2*)(&g_s[3][idx]);
      float2 s4v = *(const float2*)(&g_s[4][idx]);
      float2 s7v = *(const float2*)(&g_s[7][idx]);
      float m0v = (s1v.x+s2v.x+s3v.x+s4v.x+s5v0+s60+s7v.x+s80)*0.125f;
      float m1v = (s1v.y+s2v.y+s3v.y+s4v.y+s5v1+s61+s7v.y+s81)*0.125f;
      *(float2*)(&g_hbuf[idx]) = make_float2(m0v, m1v);
      *(__half2*)(&g_hf[idx]) = __floats2half2_rn(m0v, m1v);
      *(float2*)(&out[((size_t)row*TT + t)*NH + colb]) = make_float2(m0v, m1v);
      if (t == TT-1) *(float2*)(&out[(size_t)BB*TT*NH + idx]) = make_float2(m0v, m1v);
    }
  }
}

// ---------------- persistent scan kernel ----------------
__global__ void __launch_bounds__(NT,1) rnn_persistent(float* __restrict__ out){
  extern __shared__ __align__(16) unsigned char dsm[];
  __shared__ __align__(8) uint64_t s_mbar[3];

  const int tid = threadIdx.x;
  uint32_t sbase, mb0;
  { uint32_t a; asm("{ .reg .u64 t; cvta.to.shared.u64 t, %1; cvt.u32.u64 %0, t; }" : "=r"(a) : "l"(dsm)); sbase = a; }
  { uint32_t a; asm("{ .reg .u64 t; cvta.to.shared.u64 t, %1; cvt.u32.u64 %0, t; }" : "=r"(a) : "l"(&s_mbar[0])); mb0 = a; }

  if (tid == 0){
    #pragma unroll
    for (int b=0;b<3;b++)
      asm volatile("mbarrier.init.shared.b64 [%0], %1;" :: "r"(mb0+b*8), "r"(1u) : "memory");
  }
  __syncthreads();

  int ph[3] = {0,0,0};
  unsigned target = 0;

  for (int t = 0; t < TT; t++){
    // G0: [x_t | h] @ W0 -> s0 (tanh, resid h). 128 jobs, K=2048
    for (int it = blockIdx.x; it < 128; it += gridDim.x){
      int m0 = (it >= 64) ? 64 : 0, j0 = (it & 63)*16;
      job<false>(g_xf + (size_t)t*NI, (long)TT*NI, g_hf,
                 g_W0t, nullptr, 2048, g_hbuf, g_s[0], g_sf[0],
                 m0, j0, 3, 8, sbase, mb0, ph, tid, out, t);
    }
    gsync(target);

    // G1: gene0 (sigmoid) s0 -> s1. 128 jobs, K=1024
    for (int it = blockIdx.x; it < 128; it += gridDim.x){
      int m0 = (it >= 64) ? 64 : 0, j0 = (it & 63)*16;
      job<false>(g_sf[0], NH, nullptr, g_Wst[0], nullptr, 1024,
                 g_s[0], g_s[1], g_sf[1], m0, j0, 0, 4, sbase, mb0, ph, tid, out, t);
    }
    gsync(target);

    // G2: genes 1,2,3 from s1 -> s2(relu), s3(relu), s4(identity). 384 jobs
    for (int it = blockIdx.x; it < 384; it += gridDim.x){
      int gi = 1 + (it >> 7), rem = it & 127;
      int m0 = (rem >= 64) ? 64 : 0, j0 = (rem & 63)*16;
      int dst = gi + 1;
      job<false>(g_sf[1], NH, nullptr, g_Wst[gi], nullptr, 1024,
                 g_s[1], g_s[dst], (dst < 4) ? g_sf[dst] : (__half*)nullptr,
                 m0, j0, (gi==3)?2:1, 4, sbase, mb0, ph, tid, out, t);
    }
    gsync(target);

    // G3: gene4 (tanh) s2->s5 ; gene6 (tanh) s3->s7. 256 jobs
    for (int it = blockIdx.x; it < 256; it += gridDim.x){
      int slot = it >> 7, rem = it & 127;
      int m0 = (rem >= 64) ? 64 : 0, j0 = (rem & 63)*16;
      int gi = 4 + slot*2, src = 2 + slot, dst = gi + 1;  // 5 or 7
      job<false>(g_sf[src], NH, nullptr, g_Wst[gi], nullptr, 1024,
                 g_s[src], g_s[dst], (dst==5) ? g_sf[5] : (__half*)nullptr,
                 m0, j0, 3, 4, sbase, mb0, ph, tid, out, t);
    }
    gsync(target);

    // G4+F fused: gene5+gene7 from s5 -> s6,s8 locally; h=mean(s1..s8); out writes.
    for (int it = blockIdx.x; it < 128; it += gridDim.x){
      int m0 = (it >= 64) ? 64 : 0, j0 = (it & 63)*16;
      job<true>(g_sf[5], NH, nullptr, g_Wst[5], g_Wst[7], 1024,
                g_s[5], nullptr, nullptr, m0, j0, 0, 4, sbase, mb0, ph, tid, out, t);
    }
    gsync(target);
  }
}

// ---------------- prologue helpers ----------------
__global__ void tohalf_kernel(const float* __restrict__ src, __half* __restrict__ dst,
                              float* __restrict__ fcopy, int n){
  int i = blockIdx.x*blockDim.x + threadIdx.x;
  int stride = gridDim.x*blockDim.x;
  for (; i < n; i += stride){
    float v = src[i];
    dst[i] = __float2half_rn(v);
    if (fcopy) fcopy[i] = v;
  }
}

__global__ void thalf_kernel(const float* __restrict__ in, __half* __restrict__ outh,
                             int K, int N){
  __shared__ float tile[32][33];
  const float* src = in + (size_t)blockIdx.z*K*N;
  __half* oh = outh + (size_t)blockIdx.z*N*K;
  int tx = threadIdx.x, ty = threadIdx.y;
  int n0 = blockIdx.x*32, k0 = blockIdx.y*32;
  #pragma unroll
  for (int r=0;r<4;r++)
    tile[ty + r*8][tx] = src[(size_t)(k0 + ty + r*8)*N + n0 + tx];
  __syncthreads();
  #pragma unroll
  for (int r=0;r<4;r++)
    oh[(size_t)(n0 + ty + r*8)*K + k0 + tx] = __float2half_rn(tile[tx][ty + r*8]);
}

__global__ void reset_kernel(){ g_arrive = 0; g_epoch = 0; }

// ---------------- host launch ----------------
extern "C" void kernel_launch(void* const* d_in, const int* in_sizes, int n_in,
                              void* d_out, int out_size){
  const float *x=nullptr, *h0=nullptr, *W0=nullptr, *Ws=nullptr;
  for (int i=0;i<n_in;i++){
    long n = in_sizes[i];
    if      (n == (long)BB*TT*NI)   x  = (const float*)d_in[i];
    else if (n == (long)BB*NH)      h0 = (const float*)d_in[i];
    else if (n == (long)2048*2048)  W0 = (const float*)d_in[i];
    else if (n == (long)8*NH*2048)  Ws = (const float*)d_in[i];
  }
  if (!x || !h0 || !W0 || !Ws) return;
  float* out = (float*)d_out;

  void* p;
  cudaGetSymbolAddress(&p, g_hbuf); float*  h_p  = (float*)p;
  cudaGetSymbolAddress(&p, g_hf);   __half* hf_p = (__half*)p;
  cudaGetSymbolAddress(&p, g_xf);   __half* xf_p = (__half*)p;
  cudaGetSymbolAddress(&p, g_W0t);  __half* w0_p = (__half*)p;
  cudaGetSymbolAddress(&p, g_Wst);  __half* ws_p = (__half*)p;

  cudaFuncSetAttribute(rnn_persistent, cudaFuncAttributeMaxDynamicSharedMemorySize, SMEM_DYN);

  int dev = 0, nsm = 0;
  cudaGetDevice(&dev);
  cudaDeviceGetAttribute(&nsm, cudaDevAttrMultiProcessorCount, dev);

  thalf_kernel<<<dim3(64,64,1), dim3(32,8)>>>(W0, w0_p, 2048, 2048);
  thalf_kernel<<<dim3(64,32,8), dim3(32,8)>>>(Ws, ws_p, 1024, 2048);
  tohalf_kernel<<<8192,256>>>(x, xf_p, nullptr, BB*TT*NI);
  tohalf_kernel<<<512,256>>>(h0, hf_p, h_p, BB*NH);
  reset_kernel<<<1,1>>>();

  rnn_persistent<<<nsm, NT, SMEM_DYN>>>(out);
  (void)out_size;
}